// round 10
// baseline (speedup 1.0000x reference)
#include <cuda_runtime.h>
#include <math.h>

#define B_   64
#define C_   8
#define H_   256
#define W_   256
#define N_   200
#define NT   (B_ * N_)          // 12800 targets
#define HW   (H_ * W_)          // 65536
#define NUM_CLASSES 3

#define THREADS 192
#define BLOCKS  148
#define NWARPS  (THREADS / 32)          // 6 warps/block, 888 warps total
#define NWORKW  (2 * (NT / 32))         // 800 work warps (2 per 32-target group)

// Each accumulator on its own 128B L2 line -> parallel LTS slices.
__device__ __align__(128) double       g_accB[16];   // bbox
__device__ __align__(128) double       g_accO[16];   // obj
__device__ __align__(128) double       g_accC[16];   // cls
__device__ __align__(128) unsigned int g_count[32];  // ticket

__device__ __forceinline__ float softplus_f(float x) {
    return fmaxf(x, 0.0f) + log1pf(expf(-fabsf(x)));
}

__device__ __forceinline__ float warp_sum_f(float v) {
    #pragma unroll
    for (int off = 16; off > 0; off >>= 1)
        v += __shfl_xor_sync(0xFFFFFFFFu, v, off);
    return v;
}

__global__ void __launch_bounds__(THREADS) yolo_fused_kernel(
    const float* __restrict__ pred,
    const float* __restrict__ targets,
    float* __restrict__ out)
{
    int lane = threadIdx.x & 31;
    int wid  = threadIdx.x >> 5;
    int Wg   = blockIdx.x * NWARPS + wid;   // global warp id

    // Per-warp staging for coalesced target reads (160 floats per warp).
    __shared__ float st[NWARPS][160];

    float bbox = 0.0f, obj = 0.0f, clsl = 0.0f;

    if (Wg < NWORKW) {
        int h = Wg & 1;                      // warp-uniform: 0 = ch0-3, 1 = ch4-7
        int g = Wg >> 1;                     // target group (32 targets)
        int i = g * 32 + lane;               // this thread's target, always < NT

        // Coalesced read of the warp's 32x5 target floats: 5 LDGs, 5 lines.
        const float* trow = targets + (size_t)g * 160;
        #pragma unroll
        for (int k = 0; k < 5; k++)
            st[wid][lane + 32 * k] = __ldg(trow + lane + 32 * k);
        __syncwarp();

        // Stride-5 smem read (5 coprime 32 -> conflict-free permutation).
        float cid = st[wid][5 * lane + 0];
        float c0  = st[wid][5 * lane + 1];
        float c1  = st[wid][5 * lane + 2];
        float c2  = st[wid][5 * lane + 3];
        float c3  = st[wid][5 * lane + 4];

        float csum = ((c0 + c1) + c2) + c3;
        int xp = (int)(c0 * (float)W_);
        int yp = (int)(c1 * (float)H_);
        bool valid = (cid >= 0.0f) && (csum > 0.0f);
        bool inb = (xp >= 0) && (xp < W_) && (yp >= 0) && (yp < H_);

        if (valid && inb) {
            int b = i / N_;
            int xs = min(max(xp, 0), W_ - 1);
            int ys = min(max(yp, 0), H_ - 1);
            const float* base = pred + ((size_t)b * C_ + (size_t)(h * 4)) * HW
                                     + (size_t)ys * W_ + xs;

            float p0 = __ldg(base);
            float p1 = __ldg(base + HW);
            float p2 = __ldg(base + 2 * (size_t)HW);
            float p3 = __ldg(base + 3 * (size_t)HW);

            if (h == 0) {   // warp-uniform branch
                float d0 = p0 - c0, d1 = p1 - c1, d2 = p2 - c2, d3 = p3 - c3;
                bbox = 0.25f * (d0 * d0 + d1 * d1 + d2 * d2 + d3 * d3);
            } else {
                obj = softplus_f(-p0);       // bce(ch4, 1)
                int k = (int)fmaxf(cid, 0.0f);
                float s = softplus_f(p1) - (k == 0 ? p1 : 0.0f);
                s      += softplus_f(p2) - (k == 1 ? p2 : 0.0f);
                s      += softplus_f(p3) - (k == 2 ? p3 : 0.0f);
                clsl = s * (1.0f / 3.0f);
            }
        }
    }

    // Intra-warp reduce, one shared staging barrier, warp 0 finishes.
    __shared__ float sb[NWARPS], so[NWARPS], sc[NWARPS];
    bbox = warp_sum_f(bbox);
    obj  = warp_sum_f(obj);
    clsl = warp_sum_f(clsl);
    if (lane == 0) { sb[wid] = bbox; so[wid] = obj; sc[wid] = clsl; }
    __syncthreads();

    if (wid != 0) return;

    float vb = (lane < NWARPS) ? sb[lane] : 0.0f;
    float vo = (lane < NWARPS) ? so[lane] : 0.0f;
    float vc = (lane < NWARPS) ? sc[lane] : 0.0f;
    vb = warp_sum_f(vb); vo = warp_sum_f(vo); vc = warp_sum_f(vc);

    unsigned int old = 0;
    if (lane == 0) {
        atomicAdd(&g_accB[0], (double)vb);
        atomicAdd(&g_accO[0], (double)vo);
        atomicAdd(&g_accC[0], (double)vc);
        // acq_rel ticket: release orders the adds above, acquire covers the
        // last block's reads below.
        asm volatile("atom.acq_rel.gpu.add.u32 %0, [%1], %2;"
                     : "=r"(old) : "l"(&g_count[0]), "r"(1u) : "memory");
    }
    old = __shfl_sync(0xFFFFFFFFu, old, 0);

    if (old == (unsigned int)(BLOCKS - 1) && lane == 0) {
        double bs = __ldcg(&g_accB[0]);
        double os = __ldcg(&g_accO[0]);
        double cs = __ldcg(&g_accC[0]);
        double total = 0.05 * bs + 1.0 * os + 0.5 * cs;
        out[0] = (float)total;
        out[1] = (float)bs;
        out[2] = (float)os;
        out[3] = (float)cs;
        // Reset for next graph replay.
        __stcg(&g_accB[0], 0.0);
        __stcg(&g_accO[0], 0.0);
        __stcg(&g_accC[0], 0.0);
        g_count[0] = 0;
    }
}

extern "C" void kernel_launch(void* const* d_in, const int* in_sizes, int n_in,
                              void* d_out, int out_size)
{
    const float* pred    = (const float*)d_in[0];
    const float* targets = (const float*)d_in[1];
    float* out = (float*)d_out;

    yolo_fused_kernel<<<BLOCKS, THREADS>>>(pred, targets, out);
}

// round 11
// speedup vs baseline: 1.0448x; 1.0448x over previous
#include <cuda_runtime.h>
#include <math.h>

#define B_   64
#define C_   8
#define H_   256
#define W_   256
#define N_   200
#define NT   (B_ * N_)          // 12800 targets
#define HW   (H_ * W_)          // 65536
#define NUM_CLASSES 3

#define THREADS 384
#define BLOCKS  74
#define NWARPS  (THREADS / 32)          // 12 warps/block, 888 warps total
#define NWORKW  (2 * (NT / 32))         // 800 work warps (2 per 32-target group)

// Each accumulator on its own 128B L2 line -> parallel LTS slices.
__device__ __align__(128) double       g_accB[16];   // bbox
__device__ __align__(128) double       g_accO[16];   // obj
__device__ __align__(128) double       g_accC[16];   // cls
__device__ __align__(128) unsigned int g_count[32];  // ticket

__device__ __forceinline__ float softplus_f(float x) {
    return fmaxf(x, 0.0f) + log1pf(expf(-fabsf(x)));
}

__device__ __forceinline__ float warp_sum_f(float v) {
    #pragma unroll
    for (int off = 16; off > 0; off >>= 1)
        v += __shfl_xor_sync(0xFFFFFFFFu, v, off);
    return v;
}

__global__ void __launch_bounds__(THREADS) yolo_fused_kernel(
    const float* __restrict__ pred,
    const float* __restrict__ targets,
    float* __restrict__ out)
{
    int lane = threadIdx.x & 31;
    int wid  = threadIdx.x >> 5;
    int Wg   = blockIdx.x * NWARPS + wid;   // global warp id

    float bbox = 0.0f, obj = 0.0f, clsl = 0.0f;

    if (Wg < NWORKW) {
        int h = Wg & 1;                      // warp-uniform: 0 = ch0-3, 1 = ch4-7
        int i = (Wg >> 1) * 32 + lane;       // target index, always < NT

        const float* t = targets + (size_t)i * 5;
        float cid = __ldg(t + 0);
        float c0 = __ldg(t + 1), c1 = __ldg(t + 2);
        float c2 = __ldg(t + 3), c3 = __ldg(t + 4);

        float csum = ((c0 + c1) + c2) + c3;
        int xp = (int)(c0 * (float)W_);
        int yp = (int)(c1 * (float)H_);
        bool valid = (cid >= 0.0f) && (csum > 0.0f);
        bool inb = (xp >= 0) && (xp < W_) && (yp >= 0) && (yp < H_);

        if (valid && inb) {
            int b = i / N_;
            int xs = min(max(xp, 0), W_ - 1);
            int ys = min(max(yp, 0), H_ - 1);
            const float* base = pred + ((size_t)b * C_ + (size_t)(h * 4)) * HW
                                     + (size_t)ys * W_ + xs;

            float p0 = __ldg(base);
            float p1 = __ldg(base + HW);
            float p2 = __ldg(base + 2 * (size_t)HW);
            float p3 = __ldg(base + 3 * (size_t)HW);

            if (h == 0) {   // warp-uniform branch
                float d0 = p0 - c0, d1 = p1 - c1, d2 = p2 - c2, d3 = p3 - c3;
                bbox = 0.25f * (d0 * d0 + d1 * d1 + d2 * d2 + d3 * d3);
            } else {
                obj = softplus_f(-p0);       // bce(ch4, 1)
                int k = (int)fmaxf(cid, 0.0f);
                float s = softplus_f(p1) - (k == 0 ? p1 : 0.0f);
                s      += softplus_f(p2) - (k == 1 ? p2 : 0.0f);
                s      += softplus_f(p3) - (k == 2 ? p3 : 0.0f);
                clsl = s * (1.0f / 3.0f);
            }
        }
    }

    // Intra-warp reduce, one shared staging barrier, warp 0 finishes.
    __shared__ float sb[NWARPS], so[NWARPS], sc[NWARPS];
    bbox = warp_sum_f(bbox);
    obj  = warp_sum_f(obj);
    clsl = warp_sum_f(clsl);
    if (lane == 0) { sb[wid] = bbox; so[wid] = obj; sc[wid] = clsl; }
    __syncthreads();

    if (wid != 0) return;

    float vb = (lane < NWARPS) ? sb[lane] : 0.0f;
    float vo = (lane < NWARPS) ? so[lane] : 0.0f;
    float vc = (lane < NWARPS) ? sc[lane] : 0.0f;
    vb = warp_sum_f(vb); vo = warp_sum_f(vo); vc = warp_sum_f(vc);

    unsigned int old = 0;
    if (lane == 0) {
        atomicAdd(&g_accB[0], (double)vb);
        atomicAdd(&g_accO[0], (double)vo);
        atomicAdd(&g_accC[0], (double)vc);
        // acq_rel ticket: release orders the adds above, acquire covers the
        // last block's reads below.
        asm volatile("atom.acq_rel.gpu.add.u32 %0, [%1], %2;"
                     : "=r"(old) : "l"(&g_count[0]), "r"(1u) : "memory");
    }
    old = __shfl_sync(0xFFFFFFFFu, old, 0);

    if (old == (unsigned int)(BLOCKS - 1) && lane == 0) {
        double bs = __ldcg(&g_accB[0]);
        double os = __ldcg(&g_accO[0]);
        double cs = __ldcg(&g_accC[0]);
        double total = 0.05 * bs + 1.0 * os + 0.5 * cs;
        out[0] = (float)total;
        out[1] = (float)bs;
        out[2] = (float)os;
        out[3] = (float)cs;
        // Reset for next graph replay.
        __stcg(&g_accB[0], 0.0);
        __stcg(&g_accO[0], 0.0);
        __stcg(&g_accC[0], 0.0);
        g_count[0] = 0;
    }
}

extern "C" void kernel_launch(void* const* d_in, const int* in_sizes, int n_in,
                              void* d_out, int out_size)
{
    const float* pred    = (const float*)d_in[0];
    const float* targets = (const float*)d_in[1];
    float* out = (float*)d_out;

    yolo_fused_kernel<<<BLOCKS, THREADS>>>(pred, targets, out);
}